// round 13
// baseline (speedup 1.0000x reference)
#include <cuda_runtime.h>
#include <cstdint>

// ---------------------------------------------------------------------------
// Problem constants
// ---------------------------------------------------------------------------
#define BB 32
#define LL 256
#define SS 128
#define AA 16
#define RR 4
#define M_TOK 8192        // B*L
#define K0 132            // S + R
#define K0P16 144         // padded to /16 (guard-free K loop)
#define D1 2112
#define D2 4224
#define D3 8448
#define D4 4224
#define D5 64

// GEMM geometry: CTA 128x128, BK=16, 8 warps (4x2) of 32x64.
// All operands pre-split into f16 hi/lo planes (hi = 11-bit truncate of f32,
// exactly representable in f16; lo = rn_f16(x - hi)). Mainloop = pure LDS +
// 3x m16n8k16.f16 MMA (hi*hi + lo*hi + hi*lo), fp32 accumulate.
#define BK 16
#define PITCH 24                          // f16 per smem row (16 + 8 pad) = 48B
#define PLANE_BYTES (128 * PITCH * 2)     // 6144
#define STAGE_BYTES (4 * PLANE_BYTES)     // 24576 (AH, AL, BH, BL)
#define NSTAGE 4
#define SMB (NSTAGE * STAGE_BYTES)        // 98304

// Transposed-weight plane offsets (elements), layout [n][Kpad]
#define TO1 0
#define TO2 304128                        // + 2112*144
#define TO3 9225216                       // + 4224*2112
#define TO4 44909568                      // + 8448*4224
#define TO5 80593920                      // + 4224*8448
#define WTOT2 80864256                    // + 64*4224

// ---------------------------------------------------------------------------
// Scratch (static device globals; no allocation at runtime)
// ---------------------------------------------------------------------------
__device__ uint16_t g_xh[M_TOK * K0P16];
__device__ uint16_t g_xl[M_TOK * K0P16];
__device__ uint16_t g_h1[M_TOK * D1];
__device__ uint16_t g_l1[M_TOK * D1];
__device__ uint16_t g_h2[M_TOK * D2];
__device__ uint16_t g_l2[M_TOK * D2];
__device__ uint16_t g_h3[M_TOK * D3];
__device__ uint16_t g_l3[M_TOK * D3];
__device__ uint16_t g_h4[M_TOK * D4];
__device__ uint16_t g_l4[M_TOK * D4];
__device__ uint16_t g_wh[WTOT2];
__device__ uint16_t g_wl[WTOT2];

// ---------------------------------------------------------------------------
// Helpers
// ---------------------------------------------------------------------------
__device__ __forceinline__ uint32_t smem_u32(const void* p) {
    uint32_t a;
    asm("{ .reg .u64 t; cvta.to.shared.u64 t, %1; cvt.u32.u64 %0, t; }" : "=r"(a) : "l"(p));
    return a;
}

__device__ __forceinline__ void cp16(uint32_t dst, const void* src, int pred16) {
    asm volatile("cp.async.cg.shared.global [%0], [%1], 16, %2;"
                 :: "r"(dst), "l"(src), "r"(pred16) : "memory");
}
#define CP_COMMIT() asm volatile("cp.async.commit_group;" ::: "memory")
#define CP_WAIT2()  asm volatile("cp.async.wait_group 2;" ::: "memory")

// exact 11-bit-mantissa hi by mask-truncation (fp16-exact)
__device__ __forceinline__ float hi_of(float x) {
    return __uint_as_float(__float_as_uint(x) & 0xFFFFE000u);
}
__device__ __forceinline__ uint16_t f16b(float x) {
    uint16_t r;
    asm("cvt.rn.f16.f32 %0, %1;" : "=h"(r) : "f"(x));
    return r;
}
// pack two f32 into f16x2: low half = x0, high half = x1
__device__ __forceinline__ uint32_t pk16(float x1, float x0) {
    uint32_t r;
    asm("cvt.rn.f16x2.f32 %0, %1, %2;" : "=r"(r) : "f"(x1), "f"(x0));
    return r;
}

__device__ __forceinline__ void mma16f(float* c, const uint32_t* a, const uint32_t* b) {
    asm volatile(
        "mma.sync.aligned.m16n8k16.row.col.f32.f16.f16.f32 "
        "{%0,%1,%2,%3},{%4,%5,%6,%7},{%8,%9},{%0,%1,%2,%3};\n"
        : "+f"(c[0]), "+f"(c[1]), "+f"(c[2]), "+f"(c[3])
        : "r"(a[0]), "r"(a[1]), "r"(a[2]), "r"(a[3]), "r"(b[0]), "r"(b[1]));
}

// ---------------------------------------------------------------------------
// Weight transpose + split: W[k][n] f32 -> Wh/Wl[n][Kpad] f16 (zero-pad k>=KW)
// ---------------------------------------------------------------------------
__global__ void k_wtr(const float* __restrict__ W, uint16_t* __restrict__ Wh,
                      uint16_t* __restrict__ Wl, int KW, int N, int Kpad) {
    __shared__ float tile[32][33];
    const int kb = blockIdx.y * 32, nb = blockIdx.x * 32;
    const int tx = threadIdx.x, ty = threadIdx.y;      // 32 x 8
#pragma unroll
    for (int i = ty; i < 32; i += 8) {
        int k = kb + i, n = nb + tx;
        tile[i][tx] = (k < KW && n < N) ? W[(long)k * N + n] : 0.0f;
    }
    __syncthreads();
#pragma unroll
    for (int i = ty; i < 32; i += 8) {
        int n = nb + i, k = kb + tx;
        if (n < N && k < Kpad) {
            float v = tile[tx][i];
            float h = hi_of(v);
            Wh[(long)n * Kpad + k] = f16b(h);
            Wl[(long)n * Kpad + k] = f16b(v - h);
        }
    }
}

// ---------------------------------------------------------------------------
// Concat + split: x0 planes [row][144], 0:128 state, 128:132 pref, 132:144 = 0
// ---------------------------------------------------------------------------
__global__ void k_concat(const float* __restrict__ st, const float* __restrict__ pf,
                         uint16_t* __restrict__ xh, uint16_t* __restrict__ xl) {
    int idx = blockIdx.x * blockDim.x + threadIdx.x;
    if (idx >= M_TOK * K0P16) return;
    int row = idx / K0P16;
    int c   = idx - row * K0P16;
    float v;
    if (c < SS)       v = st[row * SS + c];
    else if (c < K0)  v = pf[row * RR + (c - SS)];
    else              v = 0.0f;
    float h = hi_of(v);
    xh[idx] = f16b(h);
    xl[idx] = f16b(v - h);
}

// ---------------------------------------------------------------------------
// GEMM: out = act(A @ W + bias); A,B given as f16 hi/lo planes (pitch KA).
// OUT16: write hi/lo f16 planes (layers 1-4); else f32 C (layer 5).
// ---------------------------------------------------------------------------
template <bool RELU, bool OUT16>
__global__ __launch_bounds__(256, 2)
void k_gemm(const uint16_t* __restrict__ Ah, const uint16_t* __restrict__ Al,
            const uint16_t* __restrict__ Bh, const uint16_t* __restrict__ Bl,
            const float* __restrict__ bias,
            uint16_t* __restrict__ Oh, uint16_t* __restrict__ Ol,
            float* __restrict__ C, int N, int KA)
{
    extern __shared__ char smem[];
    const uint32_t sb = smem_u32(smem);

    const int tid  = threadIdx.x;
    const int bm   = blockIdx.y * 128;
    const int n0   = blockIdx.x * 128;
    const int lane = tid & 31;
    const int wid  = tid >> 5;
    const int wm   = wid & 3;          // 0..3 -> 32 rows each
    const int wn   = wid >> 2;         // 0..1 -> 64 cols each
    const int grp  = lane >> 2;
    const int tig  = lane & 3;

    // cp.async: thread -> row (tid&127), chunk c (tid>>7); 1 chunk per plane
    const int l_row = tid & 127;
    const int l_c   = tid >> 7;
    const long a_base = (long)(bm + l_row) * KA + l_c * 8;
    const int  n_ok   = (n0 + l_row) < N ? 16 : 0;
    const long b_base = (long)(n_ok ? (n0 + l_row) : 0) * KA + l_c * 8;
    const uint32_t d_base = l_row * 48 + l_c * 16;

    const int T = KA >> 4;    // KA always a multiple of 16

    auto load_stage = [&](int t, int slot) {
        uint32_t st = sb + slot * STAGE_BYTES + d_base;
        long ka = a_base + t * 16;
        long kb = b_base + t * 16;
        cp16(st,                   Ah + ka, 16);
        cp16(st + PLANE_BYTES,     Al + ka, 16);
        cp16(st + 2 * PLANE_BYTES, Bh + kb, n_ok);
        cp16(st + 3 * PLANE_BYTES, Bl + kb, n_ok);
    };

    float c[2][8][4];
#pragma unroll
    for (int mt = 0; mt < 2; mt++)
#pragma unroll
        for (int nt = 0; nt < 8; nt++)
#pragma unroll
            for (int j = 0; j < 4; j++) c[mt][nt][j] = 0.0f;

    // prologue: stages 0..2
#pragma unroll
    for (int s = 0; s < NSTAGE - 1; s++) {
        if (s < T) load_stage(s, s);
        CP_COMMIT();
    }

    for (int t = 0; t < T; t++) {
        CP_WAIT2();
        __syncthreads();
        {
            int lt = t + NSTAGE - 1;
            if (lt < T) load_stage(lt, lt & (NSTAGE - 1));
            CP_COMMIT();
        }
        const int slot = t & (NSTAGE - 1);
        const char* sAH = smem + slot * STAGE_BYTES;
        const char* sAL = sAH + PLANE_BYTES;
        const char* sBH = sAH + 2 * PLANE_BYTES;
        const char* sBL = sAH + 3 * PLANE_BYTES;

        // A fragments: pure LDS.32 (bank-conflict-free, pitch 12 words)
        uint32_t aH[2][4], aL[2][4];
#pragma unroll
        for (int mt = 0; mt < 2; mt++) {
            int R = wm * 32 + mt * 16 + grp;
#pragma unroll
            for (int kp = 0; kp < 2; kp++) {
#pragma unroll
                for (int rr = 0; rr < 2; rr++) {
                    int off = (R + 8 * rr) * 48 + kp * 16 + tig * 4;
                    aH[mt][kp * 2 + rr] = *(const uint32_t*)(sAH + off);
                    aL[mt][kp * 2 + rr] = *(const uint32_t*)(sAL + off);
                }
            }
        }

        // B fragments + 3-term MMAs
#pragma unroll
        for (int nt = 0; nt < 8; nt++) {
            int cb = wn * 64 + nt * 8 + grp;
            uint32_t bH[2], bL[2];
#pragma unroll
            for (int kp = 0; kp < 2; kp++) {
                int off = cb * 48 + kp * 16 + tig * 4;
                bH[kp] = *(const uint32_t*)(sBH + off);
                bL[kp] = *(const uint32_t*)(sBL + off);
            }
            mma16f(c[0][nt], aH[0], bH);   // hi*hi
            mma16f(c[0][nt], aL[0], bH);   // lo*hi
            mma16f(c[0][nt], aH[0], bL);   // hi*lo
            mma16f(c[1][nt], aH[1], bH);
            mma16f(c[1][nt], aL[1], bH);
            mma16f(c[1][nt], aH[1], bL);
        }
    }

    // epilogue
#pragma unroll
    for (int mt = 0; mt < 2; mt++) {
        int r = bm + wm * 32 + mt * 16 + grp;
#pragma unroll
        for (int nt = 0; nt < 8; nt++) {
            int col = n0 + wn * 64 + nt * 8 + tig * 2;
            if (col < N) {
                float bv0 = bias[col], bv1 = bias[col + 1];
                float v0 = c[mt][nt][0] + bv0;
                float v1 = c[mt][nt][1] + bv1;
                float v2 = c[mt][nt][2] + bv0;
                float v3 = c[mt][nt][3] + bv1;
                if (RELU) {
                    v0 = fmaxf(v0, 0.f); v1 = fmaxf(v1, 0.f);
                    v2 = fmaxf(v2, 0.f); v3 = fmaxf(v3, 0.f);
                }
                if (OUT16) {
                    float h0 = hi_of(v0), h1 = hi_of(v1);
                    float h2 = hi_of(v2), h3 = hi_of(v3);
                    long o0 = ((long)r * N + col) * 2;
                    long o1 = ((long)(r + 8) * N + col) * 2;
                    *(uint32_t*)((char*)Oh + o0) = pk16(h1, h0);
                    *(uint32_t*)((char*)Ol + o0) = pk16(v1 - h1, v0 - h0);
                    *(uint32_t*)((char*)Oh + o1) = pk16(h3, h2);
                    *(uint32_t*)((char*)Ol + o1) = pk16(v3 - h3, v2 - h2);
                } else {
                    C[(long)r * N + col]           = v0;
                    C[(long)r * N + col + 1]       = v1;
                    C[(long)(r + 8) * N + col]     = v2;
                    C[(long)(r + 8) * N + col + 1] = v3;
                }
            }
        }
    }
}

// ---------------------------------------------------------------------------
// _H epilogue (exact replication of reference index gymnastics).
// ---------------------------------------------------------------------------
__global__ void k_h(const float* __restrict__ q, const float* __restrict__ w,
                    float* __restrict__ hq) {
    const int i  = blockIdx.x;   // 0..31
    const int l2 = threadIdx.x;  // 0..255
    __shared__ int   s_ind[LL];
    __shared__ float s_sel[LL * 4];

    const int rsel = l2 >> 6;
    const int lb   = (l2 & 63) * 4;

    const float w0 = w[(i * LL + l2) * RR + 0];
    const float w1 = w[(i * LL + l2) * RR + 1];
    const float w2 = w[(i * LL + l2) * RR + 2];
    const float w3 = w[(i * LL + l2) * RR + 3];

    float best = -3.402823466e38f;
    int bk = 0;
    const int nb = (64 * i) & 511;
    for (int k = 0; k < 64; ++k) {
        int n  = (nb + k) & 511;
        int bp = n >> 4, a = n & 15;
        int sbp = (bp >> 2) + ((bp & 3) << 3);
        const float* qp = q + ((long)(sbp * LL + lb) * AA + a) * RR + rsel;
        float u = qp[0] * w0 + qp[64] * w1 + qp[128] * w2 + qp[192] * w3;
        if (u > best) { best = u; bk = k; }
    }
    s_ind[l2] = bk;
    {
        int n  = (nb + bk) & 511;
        int bp = n >> 4, a = n & 15;
        int sbp = (bp >> 2) + ((bp & 3) << 3);
        const float* qp = q + ((long)(sbp * LL + lb) * AA + a) * RR + rsel;
        s_sel[l2 * 4 + 0] = qp[0];
        s_sel[l2 * 4 + 1] = qp[64];
        s_sel[l2 * 4 + 2] = qp[128];
        s_sel[l2 * 4 + 3] = qp[192];
    }
    __syncthreads();

    int key = bk, pos = 0;
    for (int j = 0; j < LL; ++j) {
        int kj = s_ind[j];
        pos += (kj < key) || (kj == key && j < l2);
    }
    float* o = hq + (long)(i * LL + pos) * 4;
    o[0] = s_sel[l2 * 4 + 0];
    o[1] = s_sel[l2 * 4 + 1];
    o[2] = s_sel[l2 * 4 + 2];
    o[3] = s_sel[l2 * 4 + 3];
}

// ---------------------------------------------------------------------------
// Launch
// ---------------------------------------------------------------------------
extern "C" void kernel_launch(void* const* d_in, const int* in_sizes, int n_in,
                              void* d_out, int out_size) {
    const float* state = (const float*)d_in[0];
    const float* pref  = (const float*)d_in[1];
    const float* W1 = (const float*)d_in[3];
    const float* b1 = (const float*)d_in[4];
    const float* W2 = (const float*)d_in[5];
    const float* b2 = (const float*)d_in[6];
    const float* W3 = (const float*)d_in[7];
    const float* b3 = (const float*)d_in[8];
    const float* W4 = (const float*)d_in[9];
    const float* b4 = (const float*)d_in[10];
    const float* W5 = (const float*)d_in[11];
    const float* b5 = (const float*)d_in[12];

    float* out = (float*)d_out;
    float* hq  = out;                        // [8192, 4]
    float* q   = out + BB * LL * RR;         // [32, 256, 16, 4]

    uint16_t *xh, *xl, *h1, *l1, *h2, *l2s, *h3, *l3, *h4, *l4, *wh, *wl;
    cudaGetSymbolAddress((void**)&xh, g_xh);
    cudaGetSymbolAddress((void**)&xl, g_xl);
    cudaGetSymbolAddress((void**)&h1, g_h1);
    cudaGetSymbolAddress((void**)&l1, g_l1);
    cudaGetSymbolAddress((void**)&h2, g_h2);
    cudaGetSymbolAddress((void**)&l2s, g_l2);
    cudaGetSymbolAddress((void**)&h3, g_h3);
    cudaGetSymbolAddress((void**)&l3, g_l3);
    cudaGetSymbolAddress((void**)&h4, g_h4);
    cudaGetSymbolAddress((void**)&l4, g_l4);
    cudaGetSymbolAddress((void**)&wh, g_wh);
    cudaGetSymbolAddress((void**)&wl, g_wl);

    cudaFuncSetAttribute(k_gemm<true, true>,   cudaFuncAttributeMaxDynamicSharedMemorySize, SMB);
    cudaFuncSetAttribute(k_gemm<false, false>, cudaFuncAttributeMaxDynamicSharedMemorySize, SMB);

    // weight transpose+split (per launch, ~200us)
    {
        struct { const float* w; long off; int KW, N, Kpad; } ws[5] = {
            {W1, TO1, K0, D1, K0P16}, {W2, TO2, D1, D2, D1}, {W3, TO3, D2, D3, D2},
            {W4, TO4, D3, D4, D3},    {W5, TO5, D4, D5, D4}
        };
        for (int i = 0; i < 5; i++) {
            dim3 g((ws[i].N + 31) / 32, (ws[i].Kpad + 31) / 32);
            k_wtr<<<g, dim3(32, 8)>>>(ws[i].w, wh + ws[i].off, wl + ws[i].off,
                                      ws[i].KW, ws[i].N, ws[i].Kpad);
        }
    }

    k_concat<<<(M_TOK * K0P16 + 255) / 256, 256>>>(state, pref, xh, xl);

    {
        dim3 g((D1 + 127) / 128, M_TOK / 128);
        k_gemm<true, true><<<g, 256, SMB>>>(xh, xl, wh + TO1, wl + TO1, b1,
                                            h1, l1, nullptr, D1, K0P16);
    }
    {
        dim3 g((D2 + 127) / 128, M_TOK / 128);
        k_gemm<true, true><<<g, 256, SMB>>>(h1, l1, wh + TO2, wl + TO2, b2,
                                            h2, l2s, nullptr, D2, D1);
    }
    {
        dim3 g((D3 + 127) / 128, M_TOK / 128);
        k_gemm<true, true><<<g, 256, SMB>>>(h2, l2s, wh + TO3, wl + TO3, b3,
                                            h3, l3, nullptr, D3, D2);
    }
    {
        dim3 g((D4 + 127) / 128, M_TOK / 128);
        k_gemm<true, true><<<g, 256, SMB>>>(h3, l3, wh + TO4, wl + TO4, b4,
                                            h4, l4, nullptr, D4, D3);
    }
    {
        dim3 g(1, M_TOK / 128);
        k_gemm<false, false><<<g, 256, SMB>>>(h4, l4, wh + TO5, wl + TO5, b5,
                                              nullptr, nullptr, q, D5, D4);
    }

    k_h<<<BB, LL>>>(q, pref, hq);
}

// round 14
// speedup vs baseline: 1.1974x; 1.1974x over previous
#include <cuda_runtime.h>
#include <cstdint>

// ---------------------------------------------------------------------------
// Problem constants
// ---------------------------------------------------------------------------
#define BB 32
#define LL 256
#define SS 128
#define AA 16
#define RR 4
#define M_TOK 8192        // B*L
#define K0 132            // S + R
#define K0P 144           // padded to /16 (guard-free A loop)
#define D1 2112
#define D2 4224
#define D3 8448
#define D4 4224
#define D5 64

// GEMM geometry: CTA 128x128, BK=16, 8 warps (4x2) of 32x64.
// A: raw f32 smem, split to f16 hi/lo in-register (R12 path).
// B: weights pre-split into k-pair-interleaved f16 planes Wp[k/2][n]
//    (uint32 = f16 pair). Mainloop B = pure LDS.32, zero ALU.
// 3x m16n8k16.f16 MMA (hi*hi + lo*hi + hi*lo), fp32 accumulate.
#define BK 16
#define A_STRIDE 20                       // floats per A row (16 + 4 pad)
#define A_BYTES (128 * A_STRIDE * 4)      // 10240
#define BP_PITCH 132                      // uint32 per B pair-row (128 + 4 pad)
#define BP_BYTES (8 * BP_PITCH * 4)       // 4224 per plane
#define STAGE_BYTES (A_BYTES + 2 * BP_BYTES)  // 18688
#define NSTAGE 4
#define SMB (NSTAGE * STAGE_BYTES)        // 74752

// Pair-plane offsets (uint32 elements), layout [K/2][N]
#define PO1 0
#define PO2 152064                        // + 72*2112
#define PO3 4612608                       // + 1056*4224
#define PO4 22454784                      // + 2112*8448
#define PO5 40296960                      // + 4224*4224
#define PTOT 40432128                     // + 2112*64

// ---------------------------------------------------------------------------
// Scratch (static device globals; no allocation at runtime)
// ---------------------------------------------------------------------------
__device__ float g_x0[M_TOK * K0P];
__device__ float g_a1[M_TOK * D1];
__device__ float g_a2[M_TOK * D2];
__device__ float g_a3[M_TOK * D3];
__device__ float g_a4[M_TOK * D4];
__device__ uint32_t g_wph[PTOT];
__device__ uint32_t g_wpl[PTOT];

// ---------------------------------------------------------------------------
// Helpers
// ---------------------------------------------------------------------------
__device__ __forceinline__ uint32_t smem_u32(const void* p) {
    uint32_t a;
    asm("{ .reg .u64 t; cvta.to.shared.u64 t, %1; cvt.u32.u64 %0, t; }" : "=r"(a) : "l"(p));
    return a;
}

__device__ __forceinline__ void cp16(uint32_t dst, const void* src, int pred16) {
    asm volatile("cp.async.cg.shared.global [%0], [%1], 16, %2;"
                 :: "r"(dst), "l"(src), "r"(pred16) : "memory");
}
#define CP_COMMIT() asm volatile("cp.async.commit_group;" ::: "memory")
#define CP_WAIT2()  asm volatile("cp.async.wait_group 2;" ::: "memory")

// exact 11-bit-mantissa hi by mask-truncation (fp16-exact)
__device__ __forceinline__ float hi_of(float x) {
    return __uint_as_float(__float_as_uint(x) & 0xFFFFE000u);
}
// pack two f32 into f16x2: low half = x0, high half = x1
__device__ __forceinline__ uint32_t pk16(float x1, float x0) {
    uint32_t r;
    asm("cvt.rn.f16x2.f32 %0, %1, %2;" : "=r"(r) : "f"(x1), "f"(x0));
    return r;
}

__device__ __forceinline__ void mma16f(float* c, const uint32_t* a, const uint32_t* b) {
    asm volatile(
        "mma.sync.aligned.m16n8k16.row.col.f32.f16.f16.f32 "
        "{%0,%1,%2,%3},{%4,%5,%6,%7},{%8,%9},{%0,%1,%2,%3};\n"
        : "+f"(c[0]), "+f"(c[1]), "+f"(c[2]), "+f"(c[3])
        : "r"(a[0]), "r"(a[1]), "r"(a[2]), "r"(a[3]), "r"(b[0]), "r"(b[1]));
}

// ---------------------------------------------------------------------------
// Weight pair-split: W[k][n] f32 -> Ph/Pl[k2][n] uint32 (f16 pair (2k2, 2k2+1))
// ---------------------------------------------------------------------------
__global__ void k_wpair(const float* __restrict__ W, uint32_t* __restrict__ Ph,
                        uint32_t* __restrict__ Pl, int KW, int N, long total) {
    long idx = (long)blockIdx.x * blockDim.x + threadIdx.x;  // over K2*N
    if (idx >= total) return;
    int k2 = (int)(idx / N);
    int n  = (int)(idx - (long)k2 * N);
    int k0 = 2 * k2, k1 = 2 * k2 + 1;
    float w0 = (k0 < KW) ? W[(long)k0 * N + n] : 0.0f;
    float w1 = (k1 < KW) ? W[(long)k1 * N + n] : 0.0f;
    float h0 = hi_of(w0), h1 = hi_of(w1);
    Ph[idx] = pk16(h1, h0);
    Pl[idx] = pk16(w1 - h1, w0 - h0);
}

// ---------------------------------------------------------------------------
// Concat: X0[row, 0:128] = state, [128:132] = preference, [132:144] = 0
// ---------------------------------------------------------------------------
__global__ void k_concat(const float* __restrict__ st, const float* __restrict__ pf,
                         float* __restrict__ x0) {
    int idx = blockIdx.x * blockDim.x + threadIdx.x;
    if (idx >= M_TOK * K0P) return;
    int row = idx / K0P;
    int c   = idx - row * K0P;
    float v;
    if (c < SS)       v = st[row * SS + c];
    else if (c < K0)  v = pf[row * RR + (c - SS)];
    else              v = 0.0f;
    x0[idx] = v;
}

// ---------------------------------------------------------------------------
// GEMM: C[M,N] = act(A[M,KA] @ W[KW,N] + bias)
// A f32; B as pre-split f16 pair planes. KA multiple of 16.
// ---------------------------------------------------------------------------
template <bool RELU>
__global__ __launch_bounds__(256, 2)
void k_gemm(const float* __restrict__ A, const uint32_t* __restrict__ Bph,
            const uint32_t* __restrict__ Bpl, const float* __restrict__ bias,
            float* __restrict__ C, int N, int KA)
{
    extern __shared__ char smem[];
    const uint32_t sb = smem_u32(smem);

    const int tid  = threadIdx.x;
    const int bm   = blockIdx.y * 128;
    const int n0   = blockIdx.x * 128;
    const int lane = tid & 31;
    const int wid  = tid >> 5;
    const int wm   = wid & 3;          // 0..3 -> 32 rows each
    const int wn   = wid >> 2;         // 0..1 -> 64 cols each
    const int grp  = lane >> 2;
    const int tig  = lane & 3;

    // ---- cp.async load mappings ----
    // A: 128 rows x 16k; thread -> row tid>>1, two 16B chunks at (tid&1)*2
    const int a_row = tid >> 1;
    const int a_c0  = (tid & 1) * 2;
    // B: 8 pair-rows x 128n (uint32); thread -> row tid>>5, chunk tid&31
    const int b_r = tid >> 5;
    const int b_c = tid & 31;

    const long a_rowbase = (long)(bm + a_row) * KA;
    const int  n_okc = (n0 + b_c * 4 + 4 <= N) ? 16 : 0;   // N % 4 == 0 always

    const int T = KA >> 4;

    auto load_stage = [&](int t, int slot) {
        uint32_t st = sb + slot * STAGE_BYTES;
        // A (raw f32, no k guard: KA multiple of 16, buffers padded)
        {
            uint32_t d = st + (a_row * A_STRIDE + a_c0 * 4) * 4;
            const float* s = A + a_rowbase + t * BK + a_c0 * 4;
            cp16(d,      s,     16);
            cp16(d + 16, s + 4, 16);
        }
        // B pair planes (hi, lo)
        {
            long src = (long)(t * 8 + b_r) * N + n0 + b_c * 4;
            uint32_t d = st + A_BYTES + (b_r * BP_PITCH + b_c * 4) * 4;
            cp16(d,            Bph + src, n_okc);
            cp16(d + BP_BYTES, Bpl + src, n_okc);
        }
    };

    float c[2][8][4];
#pragma unroll
    for (int mt = 0; mt < 2; mt++)
#pragma unroll
        for (int nt = 0; nt < 8; nt++)
#pragma unroll
            for (int j = 0; j < 4; j++) c[mt][nt][j] = 0.0f;

    // prologue: stages 0..2
#pragma unroll
    for (int s = 0; s < NSTAGE - 1; s++) {
        if (s < T) load_stage(s, s);
        CP_COMMIT();
    }

    for (int t = 0; t < T; t++) {
        CP_WAIT2();
        __syncthreads();
        {
            int lt = t + NSTAGE - 1;
            if (lt < T) load_stage(lt, lt & (NSTAGE - 1));
            CP_COMMIT();
        }
        const int slot = t & (NSTAGE - 1);
        const float*    As  = (const float*)(smem + slot * STAGE_BYTES);
        const uint32_t* BHs = (const uint32_t*)(smem + slot * STAGE_BYTES + A_BYTES);
        const uint32_t* BLs = BHs + 8 * BP_PITCH;

        // ---- A fp16 fragments (k16-wide), shared across the nt loop ----
        uint32_t aH[2][4], aL[2][4];
#pragma unroll
        for (int mt = 0; mt < 2; mt++) {
            int R = wm * 32 + mt * 16 + grp;
#pragma unroll
            for (int kp = 0; kp < 2; kp++) {
#pragma unroll
                for (int rr = 0; rr < 2; rr++) {
                    float2 v = *(const float2*)&As[(R + 8 * rr) * A_STRIDE + kp * 8 + 2 * tig];
                    float h0 = hi_of(v.x), h1 = hi_of(v.y);
                    aH[mt][kp * 2 + rr] = pk16(h1, h0);
                    aL[mt][kp * 2 + rr] = pk16(v.y - h1, v.x - h0);
                }
            }
        }

        // ---- B fragments (pure LDS.32) + 3-term MMAs ----
        // b0 = k-pair row tig, b1 = k-pair row 4+tig; banks 4*tig+grp all distinct
#pragma unroll
        for (int nt = 0; nt < 8; nt++) {
            int cb = wn * 64 + nt * 8 + grp;
            uint32_t bH[2], bL[2];
            bH[0] = BHs[tig * BP_PITCH + cb];
            bH[1] = BHs[(4 + tig) * BP_PITCH + cb];
            bL[0] = BLs[tig * BP_PITCH + cb];
            bL[1] = BLs[(4 + tig) * BP_PITCH + cb];
            mma16f(c[0][nt], aH[0], bH);   // hi*hi
            mma16f(c[0][nt], aL[0], bH);   // lo*hi
            mma16f(c[0][nt], aH[0], bL);   // hi*lo
            mma16f(c[1][nt], aH[1], bH);
            mma16f(c[1][nt], aL[1], bH);
            mma16f(c[1][nt], aH[1], bL);
        }
    }

    // epilogue: bias (+ relu), guarded stores
#pragma unroll
    for (int mt = 0; mt < 2; mt++) {
        int r = bm + wm * 32 + mt * 16 + grp;
#pragma unroll
        for (int nt = 0; nt < 8; nt++) {
            int col = n0 + wn * 64 + nt * 8 + tig * 2;
            if (col < N) {
                float bv0 = bias[col], bv1 = bias[col + 1];
                float v0 = c[mt][nt][0] + bv0;
                float v1 = c[mt][nt][1] + bv1;
                float v2 = c[mt][nt][2] + bv0;
                float v3 = c[mt][nt][3] + bv1;
                if (RELU) {
                    v0 = fmaxf(v0, 0.f); v1 = fmaxf(v1, 0.f);
                    v2 = fmaxf(v2, 0.f); v3 = fmaxf(v3, 0.f);
                }
                C[(long)r * N + col]           = v0;
                C[(long)r * N + col + 1]       = v1;
                C[(long)(r + 8) * N + col]     = v2;
                C[(long)(r + 8) * N + col + 1] = v3;
            }
        }
    }
}

// ---------------------------------------------------------------------------
// _H epilogue (exact replication of reference index gymnastics).
// ---------------------------------------------------------------------------
__global__ void k_h(const float* __restrict__ q, const float* __restrict__ w,
                    float* __restrict__ hq) {
    const int i  = blockIdx.x;   // 0..31
    const int l2 = threadIdx.x;  // 0..255
    __shared__ int   s_ind[LL];
    __shared__ float s_sel[LL * 4];

    const int rsel = l2 >> 6;
    const int lb   = (l2 & 63) * 4;

    const float w0 = w[(i * LL + l2) * RR + 0];
    const float w1 = w[(i * LL + l2) * RR + 1];
    const float w2 = w[(i * LL + l2) * RR + 2];
    const float w3 = w[(i * LL + l2) * RR + 3];

    float best = -3.402823466e38f;
    int bk = 0;
    const int nb = (64 * i) & 511;
    for (int k = 0; k < 64; ++k) {
        int n  = (nb + k) & 511;
        int bp = n >> 4, a = n & 15;
        int sbp = (bp >> 2) + ((bp & 3) << 3);
        const float* qp = q + ((long)(sbp * LL + lb) * AA + a) * RR + rsel;
        float u = qp[0] * w0 + qp[64] * w1 + qp[128] * w2 + qp[192] * w3;
        if (u > best) { best = u; bk = k; }
    }
    s_ind[l2] = bk;
    {
        int n  = (nb + bk) & 511;
        int bp = n >> 4, a = n & 15;
        int sbp = (bp >> 2) + ((bp & 3) << 3);
        const float* qp = q + ((long)(sbp * LL + lb) * AA + a) * RR + rsel;
        s_sel[l2 * 4 + 0] = qp[0];
        s_sel[l2 * 4 + 1] = qp[64];
        s_sel[l2 * 4 + 2] = qp[128];
        s_sel[l2 * 4 + 3] = qp[192];
    }
    __syncthreads();

    int key = bk, pos = 0;
    for (int j = 0; j < LL; ++j) {
        int kj = s_ind[j];
        pos += (kj < key) || (kj == key && j < l2);
    }
    float* o = hq + (long)(i * LL + pos) * 4;
    o[0] = s_sel[l2 * 4 + 0];
    o[1] = s_sel[l2 * 4 + 1];
    o[2] = s_sel[l2 * 4 + 2];
    o[3] = s_sel[l2 * 4 + 3];
}

// ---------------------------------------------------------------------------
// Launch
// ---------------------------------------------------------------------------
extern "C" void kernel_launch(void* const* d_in, const int* in_sizes, int n_in,
                              void* d_out, int out_size) {
    const float* state = (const float*)d_in[0];
    const float* pref  = (const float*)d_in[1];
    const float* W1 = (const float*)d_in[3];
    const float* b1 = (const float*)d_in[4];
    const float* W2 = (const float*)d_in[5];
    const float* b2 = (const float*)d_in[6];
    const float* W3 = (const float*)d_in[7];
    const float* b3 = (const float*)d_in[8];
    const float* W4 = (const float*)d_in[9];
    const float* b4 = (const float*)d_in[10];
    const float* W5 = (const float*)d_in[11];
    const float* b5 = (const float*)d_in[12];

    float* out = (float*)d_out;
    float* hq  = out;                        // [8192, 4]
    float* q   = out + BB * LL * RR;         // [32, 256, 16, 4]

    float *x0, *a1, *a2, *a3, *a4;
    uint32_t *wph, *wpl;
    cudaGetSymbolAddress((void**)&x0,  g_x0);
    cudaGetSymbolAddress((void**)&a1,  g_a1);
    cudaGetSymbolAddress((void**)&a2,  g_a2);
    cudaGetSymbolAddress((void**)&a3,  g_a3);
    cudaGetSymbolAddress((void**)&a4,  g_a4);
    cudaGetSymbolAddress((void**)&wph, g_wph);
    cudaGetSymbolAddress((void**)&wpl, g_wpl);

    cudaFuncSetAttribute(k_gemm<true>,  cudaFuncAttributeMaxDynamicSharedMemorySize, SMB);
    cudaFuncSetAttribute(k_gemm<false>, cudaFuncAttributeMaxDynamicSharedMemorySize, SMB);

    // weight pair-split (per launch, ~150us; coalesced read + write)
    {
        struct { const float* w; long off; int KW, N, K2; } ws[5] = {
            {W1, PO1, K0, D1, K0P / 2}, {W2, PO2, D1, D2, D1 / 2},
            {W3, PO3, D2, D3, D2 / 2},  {W4, PO4, D3, D4, D3 / 2},
            {W5, PO5, D4, D5, D4 / 2}
        };
        for (int i = 0; i < 5; i++) {
            long total = (long)ws[i].K2 * ws[i].N;
            int blocks = (int)((total + 255) / 256);
            k_wpair<<<blocks, 256>>>(ws[i].w, wph + ws[i].off, wpl + ws[i].off,
                                     ws[i].KW, ws[i].N, total);
        }
    }

    k_concat<<<(M_TOK * K0P + 255) / 256, 256>>>(state, pref, x0);

    {
        dim3 g((D1 + 127) / 128, M_TOK / 128);
        k_gemm<true><<<g, 256, SMB>>>(x0, wph + PO1, wpl + PO1, b1, a1, D1, K0P);
    }
    {
        dim3 g((D2 + 127) / 128, M_TOK / 128);
        k_gemm<true><<<g, 256, SMB>>>(a1, wph + PO2, wpl + PO2, b2, a2, D2, D1);
    }
    {
        dim3 g((D3 + 127) / 128, M_TOK / 128);
        k_gemm<true><<<g, 256, SMB>>>(a2, wph + PO3, wpl + PO3, b3, a3, D3, D2);
    }
    {
        dim3 g((D4 + 127) / 128, M_TOK / 128);
        k_gemm<true><<<g, 256, SMB>>>(a3, wph + PO4, wpl + PO4, b4, a4, D4, D3);
    }
    {
        dim3 g(1, M_TOK / 128);
        k_gemm<false><<<g, 256, SMB>>>(a4, wph + PO5, wpl + PO5, b5, q, D5, D4);
    }

    k_h<<<BB, LL>>>(q, pref, hq);
}